// round 13
// baseline (speedup 1.0000x reference)
#include <cuda_runtime.h>

// LongConvolution2D via custom radix-8 register FFT (512x512 zero-padded rfft2 conv), fp32.
// y = unscaled_IDFT2( DFT2(x) * DFT2(filt) )[:256,:256] + x   (norm='forward')
// Row FFTs use the real-pair trick. All shared-memory layouts bank-conflict-free.
// Column kernels use 64-thread blocks (no cross-group convoying); row kernels use
// named per-group barriers inside the FFT and block barriers only for tile phases.

#define BB 8
#define CC 64
#define HH 256
#define WW 256
#define NIMG (BB * CC)          // 512 images
#define NF 512
#define NHALF 257               // NF/2 + 1

#define GS 584                  // per-group scratch (float2): 8 * max(SR)=8*73
#define ZT 550                  // Z-tile per-pair stride (float2), skewed scrambled-slot layout
#define RPI 258                 // input tile per-pair stride (float4)
#define RPY 312                 // y-tile per-pair stride (float2), skewed scrambled slots
#define SMSZ 2336               // row-kernel block smem (float2): 4*GS

__device__ __align__(256) float2 g_xspec[(size_t)NIMG * NHALF * HH];  // [img][k2][h]
__device__ __align__(256) float2 g_kf[(size_t)CC * NHALF * NF];       // [c][k2][slot] scrambled
__device__ __align__(256) float2 g_frow[(size_t)CC * NHALF * HH];     // [c][k2][h]
__device__ __align__(256) float2 g_tw[256];                           // W512^j

__device__ __forceinline__ float2 f2add(float2 a, float2 b) { return make_float2(a.x + b.x, a.y + b.y); }
__device__ __forceinline__ float2 f2sub(float2 a, float2 b) { return make_float2(a.x - b.x, a.y - b.y); }
__device__ __forceinline__ float2 cmul(float2 a, float2 b) {
    return make_float2(a.x * b.x - a.y * b.y, a.x * b.y + a.y * b.x);
}
template <bool INV>
__device__ __forceinline__ float2 mul_mi(float2 v) {
    return INV ? make_float2(-v.y, v.x) : make_float2(v.y, -v.x);
}

template <bool INV>
__device__ __forceinline__ void dft4(float2& b0, float2& b1, float2& b2, float2& b3) {
    float2 s02 = f2add(b0, b2), d02 = f2sub(b0, b2);
    float2 s13 = f2add(b1, b3), d13 = mul_mi<INV>(f2sub(b1, b3));
    b0 = f2add(s02, s13); b2 = f2sub(s02, s13);
    b1 = f2add(d02, d13); b3 = f2sub(d02, d13);
}

template <bool INV>
__device__ __forceinline__ void dft8(float2 a[8]) {
    const float r = 0.70710678118654752440f;
    float2 u0 = f2add(a[0], a[4]), u1 = f2add(a[1], a[5]);
    float2 u2 = f2add(a[2], a[6]), u3 = f2add(a[3], a[7]);
    float2 v0 = f2sub(a[0], a[4]);
    float2 d1 = f2sub(a[1], a[5]), d2 = f2sub(a[2], a[6]), d3 = f2sub(a[3], a[7]);
    float2 v1 = INV ? make_float2(r * (d1.x - d1.y), r * (d1.x + d1.y))
                    : make_float2(r * (d1.x + d1.y), r * (d1.y - d1.x));
    float2 v2 = mul_mi<INV>(d2);
    float2 v3 = INV ? make_float2(-r * (d3.x + d3.y), r * (d3.x - d3.y))
                    : make_float2(r * (d3.y - d3.x), -r * (d3.x + d3.y));
    dft4<INV>(u0, u1, u2, u3);
    dft4<INV>(v0, v1, v2, v3);
    a[0] = u0; a[1] = v0; a[2] = u1; a[3] = v1;
    a[4] = u2; a[5] = v2; a[6] = u3; a[7] = v3;
}

// First-stage DFT8 specialized for a[4..7] == 0 (zero-padded input).
__device__ __forceinline__ void dft8_halfzero(float2 a[8]) {
    const float r = 0.70710678118654752440f;
    float2 u0 = a[0], u1 = a[1], u2 = a[2], u3 = a[3];
    float2 v0 = a[0];
    float2 v1 = make_float2(r * (a[1].x + a[1].y), r * (a[1].y - a[1].x));
    float2 v2 = make_float2(a[2].y, -a[2].x);
    float2 v3 = make_float2(r * (a[3].y - a[3].x), -r * (a[3].x + a[3].y));
    dft4<false>(u0, u1, u2, u3);
    dft4<false>(v0, v1, v2, v3);
    a[0] = u0; a[1] = v0; a[2] = u1; a[3] = v1;
    a[4] = u2; a[5] = v2; a[6] = u3; a[7] = v3;
}

__device__ __forceinline__ int bswap6(int t) { return ((t & 7) << 3) | (t >> 3); }

// Group barrier: NAMED -> bar.sync(id, 64) (per-group); else block __syncthreads.
template <bool NAMED>
__device__ __forceinline__ void gbar(int id) {
    if (NAMED) asm volatile("bar.sync %0, 64;" :: "r"(id) : "memory");
    else __syncthreads();
}

// 512-point FFT, 64 threads per transform, 8 float2 per thread.
// t = LOGICAL thread label. Input: a[r] = x[t + 64*r]. Output: a[j] = X[bswap6(t) + 64*j].
// HALF0: a[4..7]==0 specialization. PERM: physical lane holds logical bswap6(lane).
// S0BLOCK: emit a BLOCK barrier before the first scratch write (needed when the
// caller read smem regions that overlap other groups' scratch); otherwise skipped
// (fresh smem). Internal stage barriers are per-group when NAMED (id = bid).
// SR/C2: natural SR=72,C2=9; PERM SR=73,C2=8 (bank-conflict-free).
template <bool INV, bool PERM, bool HALF0, bool S0BLOCK, bool NAMED, int SR, int C2>
__device__ void fft512_r8(float2 a[8], float2* s, int t, int bid) {
    if (HALF0) dft8_halfzero(a); else dft8<INV>(a);
    {
        float2 w1 = g_tw[t];
        if (INV) w1.y = -w1.y;
        float2 w = w1;
        a[1] = cmul(a[1], w);
#pragma unroll
        for (int k = 2; k < 8; k++) { w = cmul(w, w1); a[k] = cmul(a[k], w); }
    }
    if (S0BLOCK) __syncthreads();
    int col = PERM ? bswap6(t) : t;
#pragma unroll
    for (int k = 0; k < 8; k++) s[k * SR + col] = a[k];
    gbar<NAMED>(bid);
    int u = t & 7, k2s = t >> 3;
#pragma unroll
    for (int v = 0; v < 8; v++)
        a[v] = s[k2s * SR + (PERM ? (8 * u + v) : (u + 8 * v))];
    dft8<INV>(a);
    {
        float2 w2 = g_tw[8 * u];
        if (INV) w2.y = -w2.y;
        float2 w = w2;
        a[1] = cmul(a[1], w);
#pragma unroll
        for (int k = 2; k < 8; k++) { w = cmul(w, w2); a[k] = cmul(a[k], w); }
    }
    gbar<NAMED>(bid);
#pragma unroll
    for (int k = 0; k < 8; k++) s[k2s * SR + C2 * k + u] = a[k];
    gbar<NAMED>(bid);
    int k1a = t & 7, k2f = t >> 3;
#pragma unroll
    for (int uu = 0; uu < 8; uu++) a[uu] = s[k2f * SR + C2 * k1a + uu];
    dft8<INV>(a);
    // a[k1b] = X[k2f + 8*k1a + 64*k1b] = X[bswap6(t) + 64*k1b]
}

__global__ void __launch_bounds__(256) k_init_tw() {
    int t = threadIdx.x;
    double ang = -6.283185307179586476925286766559 * (double)t / 512.0;
    double s, c;
    sincos(ang, &s, &c);
    g_tw[t] = make_float2((float)c, (float)s);
}

// Row forward FFT, PAIRED: z = row_even + i*row_odd, one complex FFT per pair.
// FFT-internal barriers are per-group (named g+1); tile phases use block barriers.
template <bool FILT>
__global__ void __launch_bounds__(256) k_row_fwd(const float* __restrict__ in) {
    __shared__ float2 sm[SMSZ];
    int tid = threadIdx.x, g = tid >> 6, t = tid & 63;
    int img = blockIdx.x >> 5;
    int h0 = (blockIdx.x & 31) << 3;
    const float* rowa = in + ((size_t)img * HH + h0 + 2 * g) * WW;
    const float* rowb = rowa + WW;
    float2 a[8];
#pragma unroll
    for (int r = 0; r < 4; r++) a[r] = make_float2(rowa[t + 64 * r], rowb[t + 64 * r]);
    fft512_r8<false, false, true, false, true, 72, 9>(a, sm + g * GS, t, g + 1);
    __syncthreads();                 // block: Z-tile regions overlap other groups' scratch
#pragma unroll
    for (int j = 0; j < 8; j++) {
        int slot = t + 64 * j;
        sm[g * ZT + slot + (slot >> 4)] = a[j];   // Z[bswap6(slot&63) + 64*(slot>>6)]
    }
    __syncthreads();
    float2* outb = (FILT ? g_frow : g_xspec) + (size_t)img * (NHALF * HH);
    for (int uu = tid; uu < 4 * NHALF; uu += 256) {
        int k = uu >> 2, p = uu & 3;
        int kc = (512 - k) & 511;
        int sa = bswap6(k & 63) + (k & 448);  sa += sa >> 4;
        int sc = bswap6(kc & 63) + (kc & 448); sc += sc >> 4;
        float2 Za = sm[p * ZT + sa];
        float2 Zc = sm[p * ZT + sc];
        float2 Xa = make_float2(0.5f * (Za.x + Zc.x), 0.5f * (Za.y - Zc.y));
        float2 Xb = make_float2(0.5f * (Za.y + Zc.y), 0.5f * (Zc.x - Za.x));
        *reinterpret_cast<float4*>(outb + (size_t)k * HH + h0 + 2 * p) =
            make_float4(Xa.x, Xa.y, Xb.x, Xb.y);
    }
}

// Filter column forward FFT: ONE column per 64-thread block.
__global__ void __launch_bounds__(64) k_col_fwd_filt() {
    __shared__ float2 sm[GS];
    int t = threadIdx.x;
    int cid = blockIdx.x;
    int c = cid / NHALF, k2 = cid - c * NHALF;
    const float2* colin = g_frow + ((size_t)c * NHALF + k2) * HH;
    float2 a[8];
#pragma unroll
    for (int r = 0; r < 4; r++) a[r] = colin[t + 64 * r];
    fft512_r8<false, false, true, false, false, 72, 9>(a, sm, t, 0);
    float2* o = g_kf + ((size_t)c * NHALF + k2) * NF;
#pragma unroll
    for (int j = 0; j < 8; j++) o[j * 64 + t] = a[j];
}

// Fused column conv: ONE column per 64-thread block. fwd FFT -> multiply (kf
// prefetched before the FFT) -> PERM inverse (natural output), keep h<256.
__global__ void __launch_bounds__(64) k_col_conv() {
    __shared__ float2 sm[GS];
    int t = threadIdx.x;
    int cid = blockIdx.x;
    int img = cid / NHALF, k2 = cid - img * NHALF;
    int c = img & (CC - 1);
    float2* col = g_xspec + ((size_t)img * NHALF + k2) * HH;
    const float2* kf = g_kf + ((size_t)c * NHALF + k2) * NF;
    float2 kfr[8];
#pragma unroll
    for (int j = 0; j < 8; j++) kfr[j] = __ldg(kf + j * 64 + t);
    float2 a[8];
#pragma unroll
    for (int r = 0; r < 4; r++) a[r] = col[t + 64 * r];
    fft512_r8<false, false, true, false, false, 72, 9>(a, sm, t, 0);
#pragma unroll
    for (int j = 0; j < 8; j++) a[j] = cmul(a[j], kfr[j]);
    fft512_r8<true, true, false, true, false, 73, 8>(a, sm, bswap6(t), 0);  // a[j]=y[t+64j]
#pragma unroll
    for (int j = 0; j < 4; j++) col[t + 64 * j] = a[j];
}

// Row inverse, PAIRED (R8-proven form): ordered gather Z = Sa + i*Sb from
// coalesced float4 tile (Hermitian mirror for idx>256); natural inverse FFT
// (scrambled output); skewed scrambled y-tile; residual add; float4 output.
__global__ void __launch_bounds__(256) k_row_inv(const float* __restrict__ x,
                                                 float* __restrict__ out) {
    __shared__ float2 sm[SMSZ];
    float4* tile4 = reinterpret_cast<float4*>(sm);
    int tid = threadIdx.x, g = tid >> 6, t = tid & 63;
    int img = blockIdx.x >> 5;
    int h0 = (blockIdx.x & 31) << 3;
    const float2* inb = g_xspec + (size_t)img * (NHALF * HH);
    for (int uu = tid; uu < 4 * NHALF; uu += 256) {
        int k = uu >> 2, p = uu & 3;
        tile4[p * RPI + k] =
            *reinterpret_cast<const float4*>(inb + (size_t)k * HH + h0 + 2 * p);
    }
    __syncthreads();
    float2 a[8];
#pragma unroll
    for (int r = 0; r < 8; r++) {
        int idx = t + 64 * r;
        if (idx <= 256) {
            float4 v = tile4[g * RPI + idx];          // Sa=(x,y) Sb=(z,w)
            a[r] = make_float2(v.x - v.w, v.y + v.z);
        } else {
            float4 w = tile4[g * RPI + (512 - idx)];
            a[r] = make_float2(w.x + w.w, w.z - w.y);
        }
    }
    // S0BLOCK: tile4 regions overlap other groups' scratch -> block barrier first.
    fft512_r8<true, false, false, true, true, 72, 9>(a, sm + g * GS, t, g + 1);
    __syncthreads();                 // block: y-tile regions overlap other scratch
#pragma unroll
    for (int j = 0; j < 4; j++) {
        int slot = t + 64 * j;
        sm[g * RPY + slot + 8 * (slot >> 5)] = a[j];    // y[bswap6(slot&63)+64*(slot>>6)]
    }
    __syncthreads();
    int i = tid & 63, r8 = tid >> 6;
#pragma unroll
    for (int rr = 0; rr < 2; rr++) {
        int row = r8 + 4 * rr;
        int p = row >> 1, e = row & 1;
        size_t rowoff = ((size_t)img * HH + h0 + row) * WW;
        float4 xv = reinterpret_cast<const float4*>(x + rowoff)[i];
        float y[4];
#pragma unroll
        for (int cc = 0; cc < 4; cc++) {
            int w = 4 * i + cc;
            int sl = bswap6(w & 63) + (w & 192);
            sl += 8 * (sl >> 5);
            float2 yv = sm[p * RPY + sl];
            y[cc] = e ? yv.y : yv.x;
        }
        reinterpret_cast<float4*>(out + rowoff)[i] =
            make_float4(y[0] + xv.x, y[1] + xv.y, y[2] + xv.z, y[3] + xv.w);
    }
}

extern "C" void kernel_launch(void* const* d_in, const int* in_sizes, int n_in,
                              void* d_out, int out_size) {
    (void)in_sizes; (void)n_in; (void)out_size;
    const float* x = (const float*)d_in[0];
    const float* filt = (const float*)d_in[1];
    float* out = (float*)d_out;

    k_init_tw<<<1, 256>>>();
    // filter path
    k_row_fwd<true><<<CC * 32, 256>>>(filt);
    k_col_fwd_filt<<<CC * NHALF, 64>>>();
    // x path
    k_row_fwd<false><<<NIMG * 32, 256>>>(x);
    k_col_conv<<<NIMG * NHALF, 64>>>();
    k_row_inv<<<NIMG * 32, 256>>>(x, out);
}

// round 14
// speedup vs baseline: 1.0910x; 1.0910x over previous
#include <cuda_runtime.h>

// LongConvolution2D via custom radix-8 register FFT (512x512 zero-padded rfft2 conv), fp32.
// y = unscaled_IDFT2( DFT2(x) * DFT2(filt) )[:256,:256] + x   (norm='forward')
// Row FFTs use the real-pair trick. All shared-memory layouts bank-conflict-free.
// Forward FFTs specialize the first DFT8 for zero-padded upper half.
// Row kernels force 8 blocks/SM via __launch_bounds__(256, 8).

#define BB 8
#define CC 64
#define HH 256
#define WW 256
#define NIMG (BB * CC)          // 512 images
#define NF 512                  // FFT length
#define NHALF 257               // NF/2 + 1

#define GS 584                  // per-group scratch (float2): 8 * max(SROW)=8*73
#define ZT 550                  // Z-tile per-pair stride (float2), skewed scrambled-slot layout
#define RPI 258                 // input tile per-pair stride (float4)
#define RPY 312                 // y-tile per-pair stride (float2), skewed scrambled slots
#define SMSZ 2336               // block smem (float2): 4*GS

// Scratch (device globals; allocation-free per harness rules)
__device__ __align__(256) float2 g_xspec[(size_t)NIMG * NHALF * HH];  // [img][k2][h] ~269.5MB
__device__ __align__(256) float2 g_kf[(size_t)CC * NHALF * NF];       // [c][k2][slot] scrambled
__device__ __align__(256) float2 g_frow[(size_t)CC * NHALF * HH];     // [c][k2][h]
__device__ __align__(256) float2 g_tw[256];                           // W512^j, j=0..255

__device__ __forceinline__ float2 f2add(float2 a, float2 b) { return make_float2(a.x + b.x, a.y + b.y); }
__device__ __forceinline__ float2 f2sub(float2 a, float2 b) { return make_float2(a.x - b.x, a.y - b.y); }
__device__ __forceinline__ float2 cmul(float2 a, float2 b) {
    return make_float2(a.x * b.x - a.y * b.y, a.x * b.y + a.y * b.x);
}
template <bool INV>
__device__ __forceinline__ float2 mul_mi(float2 v) {
    return INV ? make_float2(-v.y, v.x) : make_float2(v.y, -v.x);
}

template <bool INV>
__device__ __forceinline__ void dft4(float2& b0, float2& b1, float2& b2, float2& b3) {
    float2 s02 = f2add(b0, b2), d02 = f2sub(b0, b2);
    float2 s13 = f2add(b1, b3), d13 = mul_mi<INV>(f2sub(b1, b3));
    b0 = f2add(s02, s13); b2 = f2sub(s02, s13);
    b1 = f2add(d02, d13); b3 = f2sub(d02, d13);
}

template <bool INV>
__device__ __forceinline__ void dft8(float2 a[8]) {
    const float r = 0.70710678118654752440f;
    float2 u0 = f2add(a[0], a[4]), u1 = f2add(a[1], a[5]);
    float2 u2 = f2add(a[2], a[6]), u3 = f2add(a[3], a[7]);
    float2 v0 = f2sub(a[0], a[4]);
    float2 d1 = f2sub(a[1], a[5]), d2 = f2sub(a[2], a[6]), d3 = f2sub(a[3], a[7]);
    float2 v1 = INV ? make_float2(r * (d1.x - d1.y), r * (d1.x + d1.y))
                    : make_float2(r * (d1.x + d1.y), r * (d1.y - d1.x));
    float2 v2 = mul_mi<INV>(d2);
    float2 v3 = INV ? make_float2(-r * (d3.x + d3.y), r * (d3.x - d3.y))
                    : make_float2(r * (d3.y - d3.x), -r * (d3.x + d3.y));
    dft4<INV>(u0, u1, u2, u3);
    dft4<INV>(v0, v1, v2, v3);
    a[0] = u0; a[1] = v0; a[2] = u1; a[3] = v1;
    a[4] = u2; a[5] = v2; a[6] = u3; a[7] = v3;
}

// First-stage DFT8 specialized for a[4..7] == 0 (zero-padded input).
__device__ __forceinline__ void dft8_halfzero(float2 a[8]) {
    const float r = 0.70710678118654752440f;
    float2 u0 = a[0], u1 = a[1], u2 = a[2], u3 = a[3];
    float2 v0 = a[0];
    float2 v1 = make_float2(r * (a[1].x + a[1].y), r * (a[1].y - a[1].x));
    float2 v2 = make_float2(a[2].y, -a[2].x);
    float2 v3 = make_float2(r * (a[3].y - a[3].x), -r * (a[3].x + a[3].y));
    dft4<false>(u0, u1, u2, u3);
    dft4<false>(v0, v1, v2, v3);
    a[0] = u0; a[1] = v0; a[2] = u1; a[3] = v1;
    a[4] = u2; a[5] = v2; a[6] = u3; a[7] = v3;
}

__device__ __forceinline__ int bswap6(int t) { return ((t & 7) << 3) | (t >> 3); }

// 512-point FFT, 64 threads per transform, 8 float2 per thread.
// t = LOGICAL thread label. Input: a[r] = x[t + 64*r]. Output: a[j] = X[bswap6(t) + 64*j].
// HALF0: input upper half (a[4..7]) is zero -> specialized first stage.
// PERM=true for calls where the physical lane holds logical label bswap6(lane)
// (scrambled input -> natural output for the inverse).
// SYNC0=false skips the leading barrier (safe only when no prior smem activity).
// SR/C2 strides per-instantiation for bank-conflict freedom:
//   natural: SR=72, C2=9;  PERM: SR=73, C2=8.
template <bool INV, bool PERM, bool HALF0, bool SYNC0, int SR, int C2>
__device__ void fft512_r8(float2 a[8], float2* s, int t) {
    if (HALF0) dft8_halfzero(a); else dft8<INV>(a);
    {
        float2 w1 = g_tw[t];
        if (INV) w1.y = -w1.y;
        float2 w = w1;
        a[1] = cmul(a[1], w);
#pragma unroll
        for (int k = 2; k < 8; k++) { w = cmul(w, w1); a[k] = cmul(a[k], w); }
    }
    if (SYNC0) __syncthreads();       // orders caller smem reads / prior FFT scratch reads
    int col = PERM ? bswap6(t) : t;
#pragma unroll
    for (int k = 0; k < 8; k++) s[k * SR + col] = a[k];
    __syncthreads();
    int u = t & 7, k2s = t >> 3;
#pragma unroll
    for (int v = 0; v < 8; v++)
        a[v] = s[k2s * SR + (PERM ? (8 * u + v) : (u + 8 * v))];
    dft8<INV>(a);
    {
        float2 w2 = g_tw[8 * u];
        if (INV) w2.y = -w2.y;
        float2 w = w2;
        a[1] = cmul(a[1], w);
#pragma unroll
        for (int k = 2; k < 8; k++) { w = cmul(w, w2); a[k] = cmul(a[k], w); }
    }
    __syncthreads();
#pragma unroll
    for (int k = 0; k < 8; k++) s[k2s * SR + C2 * k + u] = a[k];
    __syncthreads();
    int k1a = t & 7, k2f = t >> 3;
#pragma unroll
    for (int uu = 0; uu < 8; uu++) a[uu] = s[k2f * SR + C2 * k1a + uu];
    dft8<INV>(a);
    // a[k1b] = X[k2f + 8*k1a + 64*k1b] = X[bswap6(t) + 64*k1b]
}

__global__ void __launch_bounds__(256) k_init_tw() {
    int t = threadIdx.x;
    double ang = -6.283185307179586476925286766559 * (double)t / 512.0;
    double s, c;
    sincos(ang, &s, &c);
    g_tw[t] = make_float2((float)c, (float)s);
}

// Row forward FFT, PAIRED: z = row_even + i*row_odd, one complex FFT per pair.
// Z staged in skewed scrambled-slot tile (conflict-free), Hermitian split on read,
// coalesced float4 writes to [img][k][h]. Forced 8 blocks/SM.
template <bool FILT>
__global__ void __launch_bounds__(256, 8) k_row_fwd(const float* __restrict__ in) {
    __shared__ float2 sm[SMSZ];
    int tid = threadIdx.x, g = tid >> 6, t = tid & 63;
    int img = blockIdx.x >> 5;
    int h0 = (blockIdx.x & 31) << 3;
    const float* rowa = in + ((size_t)img * HH + h0 + 2 * g) * WW;
    const float* rowb = rowa + WW;
    float2 a[8];
#pragma unroll
    for (int r = 0; r < 4; r++) a[r] = make_float2(rowa[t + 64 * r], rowb[t + 64 * r]);
    fft512_r8<false, false, true, false, 72, 9>(a, sm + g * GS, t);
    __syncthreads();                 // scratch reads done in all groups; reuse smem as Z-tile
#pragma unroll
    for (int j = 0; j < 8; j++) {
        int slot = t + 64 * j;
        sm[g * ZT + slot + (slot >> 4)] = a[j];   // Z[bswap6(slot&63) + 64*(slot>>6)]
    }
    __syncthreads();
    float2* outb = (FILT ? g_frow : g_xspec) + (size_t)img * (NHALF * HH);
    for (int uu = tid; uu < 4 * NHALF; uu += 256) {
        int k = uu >> 2, p = uu & 3;
        int kc = (512 - k) & 511;
        int sa = bswap6(k & 63) + (k & 448);  sa += sa >> 4;
        int sc = bswap6(kc & 63) + (kc & 448); sc += sc >> 4;
        float2 Za = sm[p * ZT + sa];
        float2 Zc = sm[p * ZT + sc];
        float2 Xa = make_float2(0.5f * (Za.x + Zc.x), 0.5f * (Za.y - Zc.y));
        float2 Xb = make_float2(0.5f * (Za.y + Zc.y), 0.5f * (Zc.x - Za.x));
        *reinterpret_cast<float4*>(outb + (size_t)k * HH + h0 + 2 * p) =
            make_float4(Xa.x, Xa.y, Xb.x, Xb.y);
    }
}

// Filter column forward FFT: stores full scrambled spectrum (slot j*64+t).
__global__ void __launch_bounds__(256) k_col_fwd_filt() {
    __shared__ float2 sm[SMSZ];
    int tid = threadIdx.x, g = tid >> 6, t = tid & 63;
    int cid = blockIdx.x * 4 + g;
    int c = cid / NHALF, k2 = cid - c * NHALF;
    const float2* colin = g_frow + ((size_t)c * NHALF + k2) * HH;
    float2 a[8];
#pragma unroll
    for (int r = 0; r < 4; r++) a[r] = colin[t + 64 * r];
    fft512_r8<false, false, true, false, 72, 9>(a, sm + g * GS, t);
    float2* o = g_kf + ((size_t)c * NHALF + k2) * NF;
#pragma unroll
    for (int j = 0; j < 8; j++) o[j * 64 + t] = a[j];
}

// Fused column conv: fwd FFT -> multiply (kf prefetched before the FFT) -> inverse FFT
// (PERM instantiation, natural output), keep h<256.
__global__ void __launch_bounds__(256) k_col_conv() {
    __shared__ float2 sm[SMSZ];
    int tid = threadIdx.x, g = tid >> 6, t = tid & 63;
    int cid = blockIdx.x * 4 + g;
    int img = cid / NHALF, k2 = cid - img * NHALF;
    int c = img & (CC - 1);
    float2* col = g_xspec + ((size_t)img * NHALF + k2) * HH;
    // prefetch filter spectrum: latency overlaps the whole forward FFT
    const float2* kf = g_kf + ((size_t)c * NHALF + k2) * NF;
    float2 kfr[8];
#pragma unroll
    for (int j = 0; j < 8; j++) kfr[j] = __ldg(kf + j * 64 + t);
    float2 a[8];
#pragma unroll
    for (int r = 0; r < 4; r++) a[r] = col[t + 64 * r];
    fft512_r8<false, false, true, false, 72, 9>(a, sm + g * GS, t);
#pragma unroll
    for (int j = 0; j < 8; j++) a[j] = cmul(a[j], kfr[j]);
    fft512_r8<true, true, false, true, 73, 8>(a, sm + g * GS, bswap6(t));  // a[j] = y[t + 64*j]
#pragma unroll
    for (int j = 0; j < 4; j++) col[t + 64 * j] = a[j];
}

// Row inverse, PAIRED (R8-proven form): ordered gather Z = Sa + i*Sb from
// coalesced float4 tile (Hermitian mirror for idx>256); natural inverse FFT
// (scrambled output); skewed scrambled y-tile; residual add; float4 output.
// Forced 8 blocks/SM.
__global__ void __launch_bounds__(256, 8) k_row_inv(const float* __restrict__ x,
                                                    float* __restrict__ out) {
    __shared__ float2 sm[SMSZ];
    float4* tile4 = reinterpret_cast<float4*>(sm);
    int tid = threadIdx.x, g = tid >> 6, t = tid & 63;
    int img = blockIdx.x >> 5;
    int h0 = (blockIdx.x & 31) << 3;
    const float2* inb = g_xspec + (size_t)img * (NHALF * HH);
    for (int uu = tid; uu < 4 * NHALF; uu += 256) {
        int k = uu >> 2, p = uu & 3;
        tile4[p * RPI + k] =
            *reinterpret_cast<const float4*>(inb + (size_t)k * HH + h0 + 2 * p);
    }
    __syncthreads();
    float2 a[8];
#pragma unroll
    for (int r = 0; r < 8; r++) {
        int idx = t + 64 * r;
        if (idx <= 256) {
            float4 v = tile4[g * RPI + idx];          // Sa=(x,y) Sb=(z,w)
            a[r] = make_float2(v.x - v.w, v.y + v.z);
        } else {
            float4 w = tile4[g * RPI + (512 - idx)];
            a[r] = make_float2(w.x + w.w, w.z - w.y);
        }
    }
    // SYNC0=true: tile4 regions overlap other groups' scratch -> block barrier first.
    fft512_r8<true, false, false, true, 72, 9>(a, sm + g * GS, t);
    __syncthreads();                 // scratch done; reuse smem as y-tile
#pragma unroll
    for (int j = 0; j < 4; j++) {
        int slot = t + 64 * j;
        sm[g * RPY + slot + 8 * (slot >> 5)] = a[j];    // y[bswap6(slot&63)+64*(slot>>6)]
    }
    __syncthreads();
    int i = tid & 63, r8 = tid >> 6;
#pragma unroll
    for (int rr = 0; rr < 2; rr++) {
        int row = r8 + 4 * rr;
        int p = row >> 1, e = row & 1;
        size_t rowoff = ((size_t)img * HH + h0 + row) * WW;
        float4 xv = reinterpret_cast<const float4*>(x + rowoff)[i];
        float y[4];
#pragma unroll
        for (int cc = 0; cc < 4; cc++) {
            int w = 4 * i + cc;
            int sl = bswap6(w & 63) + (w & 192);
            sl += 8 * (sl >> 5);
            float2 yv = sm[p * RPY + sl];
            y[cc] = e ? yv.y : yv.x;
        }
        reinterpret_cast<float4*>(out + rowoff)[i] =
            make_float4(y[0] + xv.x, y[1] + xv.y, y[2] + xv.z, y[3] + xv.w);
    }
}

extern "C" void kernel_launch(void* const* d_in, const int* in_sizes, int n_in,
                              void* d_out, int out_size) {
    (void)in_sizes; (void)n_in; (void)out_size;
    const float* x = (const float*)d_in[0];
    const float* filt = (const float*)d_in[1];
    float* out = (float*)d_out;

    k_init_tw<<<1, 256>>>();
    // filter path
    k_row_fwd<true><<<CC * 32, 256>>>(filt);
    k_col_fwd_filt<<<(CC * NHALF) / 4, 256>>>();
    // x path
    k_row_fwd<false><<<NIMG * 32, 256>>>(x);
    k_col_conv<<<(NIMG * NHALF) / 4, 256>>>();
    k_row_inv<<<NIMG * 32, 256>>>(x, out);
}

// round 15
// speedup vs baseline: 1.1013x; 1.0095x over previous
#include <cuda_runtime.h>

// LongConvolution2D via custom radix-8 register FFT (512x512 zero-padded rfft2 conv), fp32.
// y = unscaled_IDFT2( DFT2(x) * DFT2(filt) )[:256,:256] + x   (norm='forward')
// Row FFTs use the real-pair trick. All shared-memory layouts bank-conflict-free.
// Launch graph: filter path (row FFTs + column FFTs) runs on a forked stream,
// overlapped with the x row pass; joined by event before the fused column conv.

#define BB 8
#define CC 64
#define HH 256
#define WW 256
#define NIMG (BB * CC)          // 512 images
#define NF 512                  // FFT length
#define NHALF 257               // NF/2 + 1

#define GS 584                  // per-group scratch (float2): 8 * max(SROW)=8*73
#define ZT 550                  // Z-tile per-pair stride (float2), skewed scrambled-slot layout
#define RPI 258                 // input tile per-pair stride (float4)
#define RPY 312                 // y-tile per-pair stride (float2), skewed scrambled slots
#define SMSZ 2336               // block smem (float2): 4*GS

// Scratch (device globals; allocation-free per harness rules)
__device__ __align__(256) float2 g_xspec[(size_t)NIMG * NHALF * HH];  // [img][k2][h] ~269.5MB
__device__ __align__(256) float2 g_kf[(size_t)CC * NHALF * NF];       // [c][k2][slot] scrambled
__device__ __align__(256) float2 g_frow[(size_t)CC * NHALF * HH];     // [c][k2][h]
__device__ __align__(256) float2 g_tw[256];                           // W512^j, j=0..255

__device__ __forceinline__ float2 f2add(float2 a, float2 b) { return make_float2(a.x + b.x, a.y + b.y); }
__device__ __forceinline__ float2 f2sub(float2 a, float2 b) { return make_float2(a.x - b.x, a.y - b.y); }
__device__ __forceinline__ float2 cmul(float2 a, float2 b) {
    return make_float2(a.x * b.x - a.y * b.y, a.x * b.y + a.y * b.x);
}
template <bool INV>
__device__ __forceinline__ float2 mul_mi(float2 v) {
    return INV ? make_float2(-v.y, v.x) : make_float2(v.y, -v.x);
}

template <bool INV>
__device__ __forceinline__ void dft4(float2& b0, float2& b1, float2& b2, float2& b3) {
    float2 s02 = f2add(b0, b2), d02 = f2sub(b0, b2);
    float2 s13 = f2add(b1, b3), d13 = mul_mi<INV>(f2sub(b1, b3));
    b0 = f2add(s02, s13); b2 = f2sub(s02, s13);
    b1 = f2add(d02, d13); b3 = f2sub(d02, d13);
}

template <bool INV>
__device__ __forceinline__ void dft8(float2 a[8]) {
    const float r = 0.70710678118654752440f;
    float2 u0 = f2add(a[0], a[4]), u1 = f2add(a[1], a[5]);
    float2 u2 = f2add(a[2], a[6]), u3 = f2add(a[3], a[7]);
    float2 v0 = f2sub(a[0], a[4]);
    float2 d1 = f2sub(a[1], a[5]), d2 = f2sub(a[2], a[6]), d3 = f2sub(a[3], a[7]);
    float2 v1 = INV ? make_float2(r * (d1.x - d1.y), r * (d1.x + d1.y))
                    : make_float2(r * (d1.x + d1.y), r * (d1.y - d1.x));
    float2 v2 = mul_mi<INV>(d2);
    float2 v3 = INV ? make_float2(-r * (d3.x + d3.y), r * (d3.x - d3.y))
                    : make_float2(r * (d3.y - d3.x), -r * (d3.x + d3.y));
    dft4<INV>(u0, u1, u2, u3);
    dft4<INV>(v0, v1, v2, v3);
    a[0] = u0; a[1] = v0; a[2] = u1; a[3] = v1;
    a[4] = u2; a[5] = v2; a[6] = u3; a[7] = v3;
}

// First-stage DFT8 specialized for a[4..7] == 0 (zero-padded input).
__device__ __forceinline__ void dft8_halfzero(float2 a[8]) {
    const float r = 0.70710678118654752440f;
    float2 u0 = a[0], u1 = a[1], u2 = a[2], u3 = a[3];
    float2 v0 = a[0];
    float2 v1 = make_float2(r * (a[1].x + a[1].y), r * (a[1].y - a[1].x));
    float2 v2 = make_float2(a[2].y, -a[2].x);
    float2 v3 = make_float2(r * (a[3].y - a[3].x), -r * (a[3].x + a[3].y));
    dft4<false>(u0, u1, u2, u3);
    dft4<false>(v0, v1, v2, v3);
    a[0] = u0; a[1] = v0; a[2] = u1; a[3] = v1;
    a[4] = u2; a[5] = v2; a[6] = u3; a[7] = v3;
}

__device__ __forceinline__ int bswap6(int t) { return ((t & 7) << 3) | (t >> 3); }

// 512-point FFT, 64 threads per transform, 8 float2 per thread.
// t = LOGICAL thread label. Input: a[r] = x[t + 64*r]. Output: a[j] = X[bswap6(t) + 64*j].
// HALF0: input upper half (a[4..7]) is zero -> specialized first stage.
// PERM=true for calls where the physical lane holds logical label bswap6(lane)
// (scrambled input -> natural output for the inverse).
// SYNC0=false skips the leading barrier (safe only when no prior smem activity).
// SR/C2 strides per-instantiation for bank-conflict freedom:
//   natural: SR=72, C2=9;  PERM: SR=73, C2=8.
template <bool INV, bool PERM, bool HALF0, bool SYNC0, int SR, int C2>
__device__ void fft512_r8(float2 a[8], float2* s, int t) {
    if (HALF0) dft8_halfzero(a); else dft8<INV>(a);
    {
        float2 w1 = g_tw[t];
        if (INV) w1.y = -w1.y;
        float2 w = w1;
        a[1] = cmul(a[1], w);
#pragma unroll
        for (int k = 2; k < 8; k++) { w = cmul(w, w1); a[k] = cmul(a[k], w); }
    }
    if (SYNC0) __syncthreads();       // orders caller smem reads / prior FFT scratch reads
    int col = PERM ? bswap6(t) : t;
#pragma unroll
    for (int k = 0; k < 8; k++) s[k * SR + col] = a[k];
    __syncthreads();
    int u = t & 7, k2s = t >> 3;
#pragma unroll
    for (int v = 0; v < 8; v++)
        a[v] = s[k2s * SR + (PERM ? (8 * u + v) : (u + 8 * v))];
    dft8<INV>(a);
    {
        float2 w2 = g_tw[8 * u];
        if (INV) w2.y = -w2.y;
        float2 w = w2;
        a[1] = cmul(a[1], w);
#pragma unroll
        for (int k = 2; k < 8; k++) { w = cmul(w, w2); a[k] = cmul(a[k], w); }
    }
    __syncthreads();
#pragma unroll
    for (int k = 0; k < 8; k++) s[k2s * SR + C2 * k + u] = a[k];
    __syncthreads();
    int k1a = t & 7, k2f = t >> 3;
#pragma unroll
    for (int uu = 0; uu < 8; uu++) a[uu] = s[k2f * SR + C2 * k1a + uu];
    dft8<INV>(a);
    // a[k1b] = X[k2f + 8*k1a + 64*k1b] = X[bswap6(t) + 64*k1b]
}

__global__ void __launch_bounds__(256) k_init_tw() {
    int t = threadIdx.x;
    double ang = -6.283185307179586476925286766559 * (double)t / 512.0;
    double s, c;
    sincos(ang, &s, &c);
    g_tw[t] = make_float2((float)c, (float)s);
}

// Row forward FFT, PAIRED: z = row_even + i*row_odd, one complex FFT per pair.
// Z staged in skewed scrambled-slot tile (conflict-free), Hermitian split on read,
// coalesced float4 writes to [img][k][h]. Forced 8 blocks/SM.
template <bool FILT>
__global__ void __launch_bounds__(256, 8) k_row_fwd(const float* __restrict__ in) {
    __shared__ float2 sm[SMSZ];
    int tid = threadIdx.x, g = tid >> 6, t = tid & 63;
    int img = blockIdx.x >> 5;
    int h0 = (blockIdx.x & 31) << 3;
    const float* rowa = in + ((size_t)img * HH + h0 + 2 * g) * WW;
    const float* rowb = rowa + WW;
    float2 a[8];
#pragma unroll
    for (int r = 0; r < 4; r++) a[r] = make_float2(rowa[t + 64 * r], rowb[t + 64 * r]);
    fft512_r8<false, false, true, false, 72, 9>(a, sm + g * GS, t);
    __syncthreads();                 // scratch reads done in all groups; reuse smem as Z-tile
#pragma unroll
    for (int j = 0; j < 8; j++) {
        int slot = t + 64 * j;
        sm[g * ZT + slot + (slot >> 4)] = a[j];   // Z[bswap6(slot&63) + 64*(slot>>6)]
    }
    __syncthreads();
    float2* outb = (FILT ? g_frow : g_xspec) + (size_t)img * (NHALF * HH);
    for (int uu = tid; uu < 4 * NHALF; uu += 256) {
        int k = uu >> 2, p = uu & 3;
        int kc = (512 - k) & 511;
        int sa = bswap6(k & 63) + (k & 448);  sa += sa >> 4;
        int sc = bswap6(kc & 63) + (kc & 448); sc += sc >> 4;
        float2 Za = sm[p * ZT + sa];
        float2 Zc = sm[p * ZT + sc];
        float2 Xa = make_float2(0.5f * (Za.x + Zc.x), 0.5f * (Za.y - Zc.y));
        float2 Xb = make_float2(0.5f * (Za.y + Zc.y), 0.5f * (Zc.x - Za.x));
        *reinterpret_cast<float4*>(outb + (size_t)k * HH + h0 + 2 * p) =
            make_float4(Xa.x, Xa.y, Xb.x, Xb.y);
    }
}

// Filter column forward FFT: stores full scrambled spectrum (slot j*64+t).
__global__ void __launch_bounds__(256) k_col_fwd_filt() {
    __shared__ float2 sm[SMSZ];
    int tid = threadIdx.x, g = tid >> 6, t = tid & 63;
    int cid = blockIdx.x * 4 + g;
    int c = cid / NHALF, k2 = cid - c * NHALF;
    const float2* colin = g_frow + ((size_t)c * NHALF + k2) * HH;
    float2 a[8];
#pragma unroll
    for (int r = 0; r < 4; r++) a[r] = colin[t + 64 * r];
    fft512_r8<false, false, true, false, 72, 9>(a, sm + g * GS, t);
    float2* o = g_kf + ((size_t)c * NHALF + k2) * NF;
#pragma unroll
    for (int j = 0; j < 8; j++) o[j * 64 + t] = a[j];
}

// Fused column conv: fwd FFT -> multiply (kf prefetched before the FFT) -> inverse FFT
// (PERM instantiation, natural output), keep h<256.
__global__ void __launch_bounds__(256) k_col_conv() {
    __shared__ float2 sm[SMSZ];
    int tid = threadIdx.x, g = tid >> 6, t = tid & 63;
    int cid = blockIdx.x * 4 + g;
    int img = cid / NHALF, k2 = cid - img * NHALF;
    int c = img & (CC - 1);
    float2* col = g_xspec + ((size_t)img * NHALF + k2) * HH;
    // prefetch filter spectrum: latency overlaps the whole forward FFT
    const float2* kf = g_kf + ((size_t)c * NHALF + k2) * NF;
    float2 kfr[8];
#pragma unroll
    for (int j = 0; j < 8; j++) kfr[j] = __ldg(kf + j * 64 + t);
    float2 a[8];
#pragma unroll
    for (int r = 0; r < 4; r++) a[r] = col[t + 64 * r];
    fft512_r8<false, false, true, false, 72, 9>(a, sm + g * GS, t);
#pragma unroll
    for (int j = 0; j < 8; j++) a[j] = cmul(a[j], kfr[j]);
    fft512_r8<true, true, false, true, 73, 8>(a, sm + g * GS, bswap6(t));  // a[j] = y[t + 64*j]
#pragma unroll
    for (int j = 0; j < 4; j++) col[t + 64 * j] = a[j];
}

// Row inverse, PAIRED: ordered gather Z = Sa + i*Sb from coalesced float4 tile
// (Hermitian mirror for idx>256); natural inverse FFT (scrambled output);
// skewed scrambled y-tile; residual add; float4 output. Forced 8 blocks/SM.
__global__ void __launch_bounds__(256, 8) k_row_inv(const float* __restrict__ x,
                                                    float* __restrict__ out) {
    __shared__ float2 sm[SMSZ];
    float4* tile4 = reinterpret_cast<float4*>(sm);
    int tid = threadIdx.x, g = tid >> 6, t = tid & 63;
    int img = blockIdx.x >> 5;
    int h0 = (blockIdx.x & 31) << 3;
    const float2* inb = g_xspec + (size_t)img * (NHALF * HH);
    for (int uu = tid; uu < 4 * NHALF; uu += 256) {
        int k = uu >> 2, p = uu & 3;
        tile4[p * RPI + k] =
            *reinterpret_cast<const float4*>(inb + (size_t)k * HH + h0 + 2 * p);
    }
    __syncthreads();
    float2 a[8];
#pragma unroll
    for (int r = 0; r < 8; r++) {
        int idx = t + 64 * r;
        if (idx <= 256) {
            float4 v = tile4[g * RPI + idx];          // Sa=(x,y) Sb=(z,w)
            a[r] = make_float2(v.x - v.w, v.y + v.z);
        } else {
            float4 w = tile4[g * RPI + (512 - idx)];
            a[r] = make_float2(w.x + w.w, w.z - w.y);
        }
    }
    // SYNC0=true: tile4 regions overlap other groups' scratch -> block barrier first.
    fft512_r8<true, false, false, true, 72, 9>(a, sm + g * GS, t);
    __syncthreads();                 // scratch done; reuse smem as y-tile
#pragma unroll
    for (int j = 0; j < 4; j++) {
        int slot = t + 64 * j;
        sm[g * RPY + slot + 8 * (slot >> 5)] = a[j];    // y[bswap6(slot&63)+64*(slot>>6)]
    }
    __syncthreads();
    int i = tid & 63, r8 = tid >> 6;
#pragma unroll
    for (int rr = 0; rr < 2; rr++) {
        int row = r8 + 4 * rr;
        int p = row >> 1, e = row & 1;
        size_t rowoff = ((size_t)img * HH + h0 + row) * WW;
        float4 xv = reinterpret_cast<const float4*>(x + rowoff)[i];
        float y[4];
#pragma unroll
        for (int cc = 0; cc < 4; cc++) {
            int w = 4 * i + cc;
            int sl = bswap6(w & 63) + (w & 192);
            sl += 8 * (sl >> 5);
            float2 yv = sm[p * RPY + sl];
            y[cc] = e ? yv.y : yv.x;
        }
        reinterpret_cast<float4*>(out + rowoff)[i] =
            make_float4(y[0] + xv.x, y[1] + xv.y, y[2] + xv.z, y[3] + xv.w);
    }
}

extern "C" void kernel_launch(void* const* d_in, const int* in_sizes, int n_in,
                              void* d_out, int out_size) {
    (void)in_sizes; (void)n_in; (void)out_size;
    const float* x = (const float*)d_in[0];
    const float* filt = (const float*)d_in[1];
    float* out = (float*)d_out;

    // One-time infra (first call is the non-captured correctness run; objects
    // persist for the capture + replays). Streams/events are not device memory.
    static cudaStream_t s2 = nullptr;
    static cudaEvent_t ev_fork = nullptr, ev_join = nullptr;
    static bool use_fork = false;
    if (!s2) {
        use_fork =
            (cudaStreamCreateWithFlags(&s2, cudaStreamNonBlocking) == cudaSuccess) &&
            (cudaEventCreateWithFlags(&ev_fork, cudaEventDisableTiming) == cudaSuccess) &&
            (cudaEventCreateWithFlags(&ev_join, cudaEventDisableTiming) == cudaSuccess);
    }

    k_init_tw<<<1, 256>>>();

    if (use_fork) {
        // Fork: filter path on s2, overlapped with the x row pass on the main stream.
        cudaEventRecord(ev_fork, 0);
        cudaStreamWaitEvent(s2, ev_fork, 0);
        k_row_fwd<true><<<CC * 32, 256, 0, s2>>>(filt);
        k_col_fwd_filt<<<(CC * NHALF) / 4, 256, 0, s2>>>();
        cudaEventRecord(ev_join, s2);
        k_row_fwd<false><<<NIMG * 32, 256>>>(x);
        cudaStreamWaitEvent(0, ev_join, 0);
    } else {
        k_row_fwd<true><<<CC * 32, 256>>>(filt);
        k_col_fwd_filt<<<(CC * NHALF) / 4, 256>>>();
        k_row_fwd<false><<<NIMG * 32, 256>>>(x);
    }

    k_col_conv<<<(NIMG * NHALF) / 4, 256>>>();
    k_row_inv<<<NIMG * 32, 256>>>(x, out);
}

// round 16
// speedup vs baseline: 1.1052x; 1.0035x over previous
#include <cuda_runtime.h>

// LongConvolution2D via custom radix-8 register FFT (512x512 zero-padded rfft2 conv), fp32.
// y = unscaled_IDFT2( DFT2(x) * DFT2(filt) )[:256,:256] + x   (norm='forward')
// Row FFTs use the real-pair trick. All shared-memory layouts bank-conflict-free.
// Filter path forked onto a side stream (captured as a parallel graph branch).
// Occupancy floors: row kernels 8 blocks/SM, col_conv 6, col_fwd_filt 8.

#define BB 8
#define CC 64
#define HH 256
#define WW 256
#define NIMG (BB * CC)          // 512 images
#define NF 512                  // FFT length
#define NHALF 257               // NF/2 + 1

#define GS 584                  // per-group scratch (float2): 8 * max(SROW)=8*73
#define ZT 550                  // Z-tile per-pair stride (float2), skewed scrambled-slot layout
#define RPI 258                 // input tile per-pair stride (float4)
#define RPY 312                 // y-tile per-pair stride (float2), skewed scrambled slots
#define SMSZ 2336               // block smem (float2): 4*GS

// Scratch (device globals; allocation-free per harness rules)
__device__ __align__(256) float2 g_xspec[(size_t)NIMG * NHALF * HH];  // [img][k2][h] ~269.5MB
__device__ __align__(256) float2 g_kf[(size_t)CC * NHALF * NF];       // [c][k2][slot] scrambled
__device__ __align__(256) float2 g_frow[(size_t)CC * NHALF * HH];     // [c][k2][h]
__device__ __align__(256) float2 g_tw[256];                           // W512^j, j=0..255

__device__ __forceinline__ float2 f2add(float2 a, float2 b) { return make_float2(a.x + b.x, a.y + b.y); }
__device__ __forceinline__ float2 f2sub(float2 a, float2 b) { return make_float2(a.x - b.x, a.y - b.y); }
__device__ __forceinline__ float2 cmul(float2 a, float2 b) {
    return make_float2(a.x * b.x - a.y * b.y, a.x * b.y + a.y * b.x);
}
template <bool INV>
__device__ __forceinline__ float2 mul_mi(float2 v) {
    return INV ? make_float2(-v.y, v.x) : make_float2(v.y, -v.x);
}

template <bool INV>
__device__ __forceinline__ void dft4(float2& b0, float2& b1, float2& b2, float2& b3) {
    float2 s02 = f2add(b0, b2), d02 = f2sub(b0, b2);
    float2 s13 = f2add(b1, b3), d13 = mul_mi<INV>(f2sub(b1, b3));
    b0 = f2add(s02, s13); b2 = f2sub(s02, s13);
    b1 = f2add(d02, d13); b3 = f2sub(d02, d13);
}

template <bool INV>
__device__ __forceinline__ void dft8(float2 a[8]) {
    const float r = 0.70710678118654752440f;
    float2 u0 = f2add(a[0], a[4]), u1 = f2add(a[1], a[5]);
    float2 u2 = f2add(a[2], a[6]), u3 = f2add(a[3], a[7]);
    float2 v0 = f2sub(a[0], a[4]);
    float2 d1 = f2sub(a[1], a[5]), d2 = f2sub(a[2], a[6]), d3 = f2sub(a[3], a[7]);
    float2 v1 = INV ? make_float2(r * (d1.x - d1.y), r * (d1.x + d1.y))
                    : make_float2(r * (d1.x + d1.y), r * (d1.y - d1.x));
    float2 v2 = mul_mi<INV>(d2);
    float2 v3 = INV ? make_float2(-r * (d3.x + d3.y), r * (d3.x - d3.y))
                    : make_float2(r * (d3.y - d3.x), -r * (d3.x + d3.y));
    dft4<INV>(u0, u1, u2, u3);
    dft4<INV>(v0, v1, v2, v3);
    a[0] = u0; a[1] = v0; a[2] = u1; a[3] = v1;
    a[4] = u2; a[5] = v2; a[6] = u3; a[7] = v3;
}

// First-stage DFT8 specialized for a[4..7] == 0 (zero-padded input).
__device__ __forceinline__ void dft8_halfzero(float2 a[8]) {
    const float r = 0.70710678118654752440f;
    float2 u0 = a[0], u1 = a[1], u2 = a[2], u3 = a[3];
    float2 v0 = a[0];
    float2 v1 = make_float2(r * (a[1].x + a[1].y), r * (a[1].y - a[1].x));
    float2 v2 = make_float2(a[2].y, -a[2].x);
    float2 v3 = make_float2(r * (a[3].y - a[3].x), -r * (a[3].x + a[3].y));
    dft4<false>(u0, u1, u2, u3);
    dft4<false>(v0, v1, v2, v3);
    a[0] = u0; a[1] = v0; a[2] = u1; a[3] = v1;
    a[4] = u2; a[5] = v2; a[6] = u3; a[7] = v3;
}

__device__ __forceinline__ int bswap6(int t) { return ((t & 7) << 3) | (t >> 3); }

// 512-point FFT, 64 threads per transform, 8 float2 per thread.
// t = LOGICAL thread label. Input: a[r] = x[t + 64*r]. Output: a[j] = X[bswap6(t) + 64*j].
// HALF0: input upper half (a[4..7]) is zero -> specialized first stage.
// PERM=true for calls where the physical lane holds logical label bswap6(lane)
// (scrambled input -> natural output for the inverse).
// SYNC0=false skips the leading barrier (safe only when no prior smem activity).
// SR/C2 strides per-instantiation for bank-conflict freedom:
//   natural: SR=72, C2=9;  PERM: SR=73, C2=8.
template <bool INV, bool PERM, bool HALF0, bool SYNC0, int SR, int C2>
__device__ void fft512_r8(float2 a[8], float2* s, int t) {
    if (HALF0) dft8_halfzero(a); else dft8<INV>(a);
    {
        float2 w1 = g_tw[t];
        if (INV) w1.y = -w1.y;
        float2 w = w1;
        a[1] = cmul(a[1], w);
#pragma unroll
        for (int k = 2; k < 8; k++) { w = cmul(w, w1); a[k] = cmul(a[k], w); }
    }
    if (SYNC0) __syncthreads();       // orders caller smem reads / prior FFT scratch reads
    int col = PERM ? bswap6(t) : t;
#pragma unroll
    for (int k = 0; k < 8; k++) s[k * SR + col] = a[k];
    __syncthreads();
    int u = t & 7, k2s = t >> 3;
#pragma unroll
    for (int v = 0; v < 8; v++)
        a[v] = s[k2s * SR + (PERM ? (8 * u + v) : (u + 8 * v))];
    dft8<INV>(a);
    {
        float2 w2 = g_tw[8 * u];
        if (INV) w2.y = -w2.y;
        float2 w = w2;
        a[1] = cmul(a[1], w);
#pragma unroll
        for (int k = 2; k < 8; k++) { w = cmul(w, w2); a[k] = cmul(a[k], w); }
    }
    __syncthreads();
#pragma unroll
    for (int k = 0; k < 8; k++) s[k2s * SR + C2 * k + u] = a[k];
    __syncthreads();
    int k1a = t & 7, k2f = t >> 3;
#pragma unroll
    for (int uu = 0; uu < 8; uu++) a[uu] = s[k2f * SR + C2 * k1a + uu];
    dft8<INV>(a);
    // a[k1b] = X[k2f + 8*k1a + 64*k1b] = X[bswap6(t) + 64*k1b]
}

__global__ void __launch_bounds__(256) k_init_tw() {
    int t = threadIdx.x;
    double ang = -6.283185307179586476925286766559 * (double)t / 512.0;
    double s, c;
    sincos(ang, &s, &c);
    g_tw[t] = make_float2((float)c, (float)s);
}

// Row forward FFT, PAIRED: z = row_even + i*row_odd, one complex FFT per pair.
// Z staged in skewed scrambled-slot tile (conflict-free), Hermitian split on read,
// coalesced float4 writes to [img][k][h]. Forced 8 blocks/SM.
template <bool FILT>
__global__ void __launch_bounds__(256, 8) k_row_fwd(const float* __restrict__ in) {
    __shared__ float2 sm[SMSZ];
    int tid = threadIdx.x, g = tid >> 6, t = tid & 63;
    int img = blockIdx.x >> 5;
    int h0 = (blockIdx.x & 31) << 3;
    const float* rowa = in + ((size_t)img * HH + h0 + 2 * g) * WW;
    const float* rowb = rowa + WW;
    float2 a[8];
#pragma unroll
    for (int r = 0; r < 4; r++) a[r] = make_float2(rowa[t + 64 * r], rowb[t + 64 * r]);
    fft512_r8<false, false, true, false, 72, 9>(a, sm + g * GS, t);
    __syncthreads();                 // scratch reads done in all groups; reuse smem as Z-tile
#pragma unroll
    for (int j = 0; j < 8; j++) {
        int slot = t + 64 * j;
        sm[g * ZT + slot + (slot >> 4)] = a[j];   // Z[bswap6(slot&63) + 64*(slot>>6)]
    }
    __syncthreads();
    float2* outb = (FILT ? g_frow : g_xspec) + (size_t)img * (NHALF * HH);
    for (int uu = tid; uu < 4 * NHALF; uu += 256) {
        int k = uu >> 2, p = uu & 3;
        int kc = (512 - k) & 511;
        int sa = bswap6(k & 63) + (k & 448);  sa += sa >> 4;
        int sc = bswap6(kc & 63) + (kc & 448); sc += sc >> 4;
        float2 Za = sm[p * ZT + sa];
        float2 Zc = sm[p * ZT + sc];
        float2 Xa = make_float2(0.5f * (Za.x + Zc.x), 0.5f * (Za.y - Zc.y));
        float2 Xb = make_float2(0.5f * (Za.y + Zc.y), 0.5f * (Zc.x - Za.x));
        *reinterpret_cast<float4*>(outb + (size_t)k * HH + h0 + 2 * p) =
            make_float4(Xa.x, Xa.y, Xb.x, Xb.y);
    }
}

// Filter column forward FFT: stores full scrambled spectrum (slot j*64+t).
// Forced 8 blocks/SM (no prefetch registers; fits 32 regs like row_fwd).
__global__ void __launch_bounds__(256, 8) k_col_fwd_filt() {
    __shared__ float2 sm[SMSZ];
    int tid = threadIdx.x, g = tid >> 6, t = tid & 63;
    int cid = blockIdx.x * 4 + g;
    int c = cid / NHALF, k2 = cid - c * NHALF;
    const float2* colin = g_frow + ((size_t)c * NHALF + k2) * HH;
    float2 a[8];
#pragma unroll
    for (int r = 0; r < 4; r++) a[r] = colin[t + 64 * r];
    fft512_r8<false, false, true, false, 72, 9>(a, sm + g * GS, t);
    float2* o = g_kf + ((size_t)c * NHALF + k2) * NF;
#pragma unroll
    for (int j = 0; j < 8; j++) o[j * 64 + t] = a[j];
}

// Fused column conv: fwd FFT -> multiply (kf prefetched before the FFT) -> inverse FFT
// (PERM instantiation, natural output), keep h<256.
// Occupancy floor 6 blocks/SM (<=42 regs): a[8]+kfr[8] = 32 data regs + temps fit.
__global__ void __launch_bounds__(256, 6) k_col_conv() {
    __shared__ float2 sm[SMSZ];
    int tid = threadIdx.x, g = tid >> 6, t = tid & 63;
    int cid = blockIdx.x * 4 + g;
    int img = cid / NHALF, k2 = cid - img * NHALF;
    int c = img & (CC - 1);
    float2* col = g_xspec + ((size_t)img * NHALF + k2) * HH;
    // prefetch filter spectrum: latency overlaps the whole forward FFT
    const float2* kf = g_kf + ((size_t)c * NHALF + k2) * NF;
    float2 kfr[8];
#pragma unroll
    for (int j = 0; j < 8; j++) kfr[j] = __ldg(kf + j * 64 + t);
    float2 a[8];
#pragma unroll
    for (int r = 0; r < 4; r++) a[r] = col[t + 64 * r];
    fft512_r8<false, false, true, false, 72, 9>(a, sm + g * GS, t);
#pragma unroll
    for (int j = 0; j < 8; j++) a[j] = cmul(a[j], kfr[j]);
    fft512_r8<true, true, false, true, 73, 8>(a, sm + g * GS, bswap6(t));  // a[j] = y[t + 64*j]
#pragma unroll
    for (int j = 0; j < 4; j++) col[t + 64 * j] = a[j];
}

// Row inverse, PAIRED: ordered gather Z = Sa + i*Sb from coalesced float4 tile
// (Hermitian mirror for idx>256); natural inverse FFT (scrambled output);
// skewed scrambled y-tile; residual add; float4 output. Forced 8 blocks/SM.
__global__ void __launch_bounds__(256, 8) k_row_inv(const float* __restrict__ x,
                                                    float* __restrict__ out) {
    __shared__ float2 sm[SMSZ];
    float4* tile4 = reinterpret_cast<float4*>(sm);
    int tid = threadIdx.x, g = tid >> 6, t = tid & 63;
    int img = blockIdx.x >> 5;
    int h0 = (blockIdx.x & 31) << 3;
    const float2* inb = g_xspec + (size_t)img * (NHALF * HH);
    for (int uu = tid; uu < 4 * NHALF; uu += 256) {
        int k = uu >> 2, p = uu & 3;
        tile4[p * RPI + k] =
            *reinterpret_cast<const float4*>(inb + (size_t)k * HH + h0 + 2 * p);
    }
    __syncthreads();
    float2 a[8];
#pragma unroll
    for (int r = 0; r < 8; r++) {
        int idx = t + 64 * r;
        if (idx <= 256) {
            float4 v = tile4[g * RPI + idx];          // Sa=(x,y) Sb=(z,w)
            a[r] = make_float2(v.x - v.w, v.y + v.z);
        } else {
            float4 w = tile4[g * RPI + (512 - idx)];
            a[r] = make_float2(w.x + w.w, w.z - w.y);
        }
    }
    // SYNC0=true: tile4 regions overlap other groups' scratch -> block barrier first.
    fft512_r8<true, false, false, true, 72, 9>(a, sm + g * GS, t);
    __syncthreads();                 // scratch done; reuse smem as y-tile
#pragma unroll
    for (int j = 0; j < 4; j++) {
        int slot = t + 64 * j;
        sm[g * RPY + slot + 8 * (slot >> 5)] = a[j];    // y[bswap6(slot&63)+64*(slot>>6)]
    }
    __syncthreads();
    int i = tid & 63, r8 = tid >> 6;
#pragma unroll
    for (int rr = 0; rr < 2; rr++) {
        int row = r8 + 4 * rr;
        int p = row >> 1, e = row & 1;
        size_t rowoff = ((size_t)img * HH + h0 + row) * WW;
        float4 xv = reinterpret_cast<const float4*>(x + rowoff)[i];
        float y[4];
#pragma unroll
        for (int cc = 0; cc < 4; cc++) {
            int w = 4 * i + cc;
            int sl = bswap6(w & 63) + (w & 192);
            sl += 8 * (sl >> 5);
            float2 yv = sm[p * RPY + sl];
            y[cc] = e ? yv.y : yv.x;
        }
        reinterpret_cast<float4*>(out + rowoff)[i] =
            make_float4(y[0] + xv.x, y[1] + xv.y, y[2] + xv.z, y[3] + xv.w);
    }
}

extern "C" void kernel_launch(void* const* d_in, const int* in_sizes, int n_in,
                              void* d_out, int out_size) {
    (void)in_sizes; (void)n_in; (void)out_size;
    const float* x = (const float*)d_in[0];
    const float* filt = (const float*)d_in[1];
    float* out = (float*)d_out;

    // One-time infra (first call is the non-captured correctness run; objects
    // persist for the capture + replays). Streams/events are not device memory.
    static cudaStream_t s2 = nullptr;
    static cudaEvent_t ev_fork = nullptr, ev_join = nullptr;
    static bool use_fork = false;
    if (!s2) {
        use_fork =
            (cudaStreamCreateWithFlags(&s2, cudaStreamNonBlocking) == cudaSuccess) &&
            (cudaEventCreateWithFlags(&ev_fork, cudaEventDisableTiming) == cudaSuccess) &&
            (cudaEventCreateWithFlags(&ev_join, cudaEventDisableTiming) == cudaSuccess);
    }

    k_init_tw<<<1, 256>>>();

    if (use_fork) {
        // Fork: filter path on s2, overlapped with the x row pass on the main stream.
        cudaEventRecord(ev_fork, 0);
        cudaStreamWaitEvent(s2, ev_fork, 0);
        k_row_fwd<true><<<CC * 32, 256, 0, s2>>>(filt);
        k_col_fwd_filt<<<(CC * NHALF) / 4, 256, 0, s2>>>();
        cudaEventRecord(ev_join, s2);
        k_row_fwd<false><<<NIMG * 32, 256>>>(x);
        cudaStreamWaitEvent(0, ev_join, 0);
    } else {
        k_row_fwd<true><<<CC * 32, 256>>>(filt);
        k_col_fwd_filt<<<(CC * NHALF) / 4, 256>>>();
        k_row_fwd<false><<<NIMG * 32, 256>>>(x);
    }

    k_col_conv<<<(NIMG * NHALF) / 4, 256>>>();
    k_row_inv<<<NIMG * 32, 256>>>(x, out);
}